// round 15
// baseline (speedup 1.0000x reference)
#include <cuda_runtime.h>
#include <cuda_bf16.h>
#include <cuda_fp8.h>
#include <cstdint>
#include <math.h>

#define B_ROWS 32768
#define C_CLS  1000
#define KPAD   1024
#define EPSU   1e-6f
#define NORMF  0.031622776601683794f   // 1/sqrt(1000)
#define INV_C  0.001f
#define SA     128.0f                  // fp8 scale for A / E
#define SB     256.0f                  // fp8 scale for centered B residuals
#define DEQ    (1.0f / (128.0f * 256.0f))

// ---------------- scratch (__device__ globals; no allocations) --------------
__device__ uint8_t g_Af8[(size_t)B_ROWS * KPAD];   // p_tar  fp8 x128, padded
__device__ uint8_t g_Ef8[(size_t)B_ROWS * KPAD];   // E      fp8 x128, padded
__device__ uint8_t g_B1f8[(size_t)KPAD * KPAD];    // (bank - m1) x256  [n][k]
__device__ uint8_t g_B2f8[(size_t)KPAD * KPAD];    // (bank^T - m2) x256 [j][k]
__device__ float   g_BT[(size_t)KPAD * KPAD];      // bank^T fp32 staging
__device__ float   g_m1[KPAD];                     // row MEANS of bank
__device__ float   g_m2[KPAD];                     // raw col SUMS of bank
__device__ float   g_ptc[KPAD];                    // fast-path pt per column
__device__ float   g_eutc[KPAD];                   // fast-path eut per column
__device__ float   g_rowsum[B_ROWS];
__device__ float   g_sums[(size_t)C_CLS * C_CLS];
__device__ float   g_count[C_CLS];
__device__ int     g_nzB1;                         // residual B1 has nonzero?
__device__ int     g_nzB2;                         // residual B2 has nonzero?

// ---------------- helpers ----------------------------------------------------
__device__ __forceinline__ uint16_t f2_fp8x2(float lo, float hi) {
    __nv_fp8x2_storage_t r =
        __nv_cvt_float2_to_fp8x2(make_float2(lo, hi), __NV_SATFINITE, __NV_E4M3);
    return (uint16_t)r;
}
__device__ __forceinline__ uint32_t smem_u32(const void* p) {
    uint32_t a;
    asm("{ .reg .u64 t; cvta.to.shared.u64 t, %1; cvt.u32.u64 %0, t; }"
        : "=r"(a) : "l"(p));
    return a;
}
__device__ __forceinline__ void ldmx4(uint32_t* r, uint32_t addr) {
    asm volatile("ldmatrix.sync.aligned.m8n8.x4.shared.b16 {%0,%1,%2,%3}, [%4];"
                 : "=r"(r[0]), "=r"(r[1]), "=r"(r[2]), "=r"(r[3]) : "r"(addr));
}
__device__ __forceinline__ void mma_fp8(float* c, const uint32_t* a,
                                        uint32_t b0, uint32_t b1) {
    asm volatile("mma.sync.aligned.m16n8k32.row.col.f32.e4m3.e4m3.f32 "
                 "{%0,%1,%2,%3}, {%4,%5,%6,%7}, {%8,%9}, {%0,%1,%2,%3};"
                 : "+f"(c[0]), "+f"(c[1]), "+f"(c[2]), "+f"(c[3])
                 : "r"(a[0]), "r"(a[1]), "r"(a[2]), "r"(a[3]), "r"(b0), "r"(b1));
}
#define CP16(dst, src) \
    asm volatile("cp.async.cg.shared.global [%0], [%1], 16;" :: "r"(dst), "l"(src))
#define CP_COMMIT() asm volatile("cp.async.commit_group;")
#define CP_WAIT1()  asm volatile("cp.async.wait_group 1;")

// ---------------------------------------------------------------------------
// pre: m1 row means (blocks 0..999) + m2 col sums, deterministic (1000..1031)
//      + zero g_sums/g_count/g_rowsum/flags (1032..1287)
#define PRE_BLOCKS (1000 + 32 + 256)
__global__ void __launch_bounds__(128) pre_kernel(const float* __restrict__ bank) {
    const int b = blockIdx.x;
    const int t = threadIdx.x;
    if (b < C_CLS) {                       // ---- m1[b] = mean of row b ----
        const float* row = bank + (size_t)b * C_CLS;
        float s = 0.0f;
        for (int k = t; k < C_CLS; k += 128) s += row[k];
        #pragma unroll
        for (int o = 16; o > 0; o >>= 1) s += __shfl_xor_sync(0xFFFFFFFFu, s, o);
        __shared__ float sw[4];
        if ((t & 31) == 0) sw[t >> 5] = s;
        __syncthreads();
        if (t == 0) g_m1[b] = (sw[0] + sw[1] + sw[2] + sw[3]) * INV_C;
    } else if (b < C_CLS + 32) {           // ---- m2: 32 cols per block ----
        const int j  = (b - C_CLS) * 32 + (t & 31);
        const int rs = t >> 5;             // 0..3
        float s = 0.0f;
        if (j < C_CLS)
            for (int k = rs; k < C_CLS; k += 4)
                s += bank[(size_t)k * C_CLS + j];
        __shared__ float sm[4][32];
        sm[rs][t & 31] = s;
        __syncthreads();
        if (rs == 0 && j < C_CLS)
            g_m2[j] = sm[0][t & 31] + sm[1][t & 31] + sm[2][t & 31] + sm[3][t & 31];
    } else {                               // ---- zero scratch ----
        const int zi = (b - C_CLS - 32) * 128 + t;    // 0..32767
        float4 z4 = make_float4(0.f, 0.f, 0.f, 0.f);
        for (int i = zi; i < (C_CLS * C_CLS) / 4; i += 256 * 128)
            reinterpret_cast<float4*>(g_sums)[i] = z4;
        if (zi < C_CLS) g_count[zi] = 0.0f;
        g_rowsum[zi] = 0.0f;
        if (zi == 0) { g_nzB1 = 0; g_nzB2 = 0; }
    }
}

// flags: one 4MB pass over bank -> nzB1/nzB2 (bit-exact same fp8 rounding as
// the materializers, same g_m1/g_m2 inputs) + ptc/eutc (block 0)
__global__ void __launch_bounds__(128) flags_kernel(const float* __restrict__ bank) {
    const int k = blockIdx.x;              // bank row 0..999
    const int t = threadIdx.x;
    if (k == 0) {
        for (int j = t; j < C_CLS; j += 128) {
            float m = g_m2[j] * INV_C;
            g_ptc[j]  = m;
            g_eutc[j] = __expf(m * __logf(m + EPSU));
        }
    }
    const float m1k = g_m1[k];
    const float4* row = reinterpret_cast<const float4*>(bank + (size_t)k * C_CLS);
    uint32_t nz1 = 0u, nz2 = 0u;
    for (int u = t; u < C_CLS / 4; u += 128) {
        float4 v = row[u];
        const int j = 4 * u;
        // B1 residual (row-centered): matches convB1 materialization exactly
        uint32_t p1 = (uint32_t)f2_fp8x2((v.x - m1k) * SB, (v.y - m1k) * SB)
                    | ((uint32_t)f2_fp8x2((v.z - m1k) * SB, (v.w - m1k) * SB) << 16);
        nz1 |= (p1 & 0x7F7F7F7Fu);
        // B2 residual (col-centered): matches convB2 materialization exactly
        float ma = g_m2[j + 0] * INV_C;
        float mb = g_m2[j + 1] * INV_C;
        float mc = g_m2[j + 2] * INV_C;
        float md = g_m2[j + 3] * INV_C;
        uint32_t p2 = (uint32_t)f2_fp8x2((v.x - ma) * SB, (v.y - mb) * SB)
                    | ((uint32_t)f2_fp8x2((v.z - mc) * SB, (v.w - md) * SB) << 16);
        nz2 |= (p2 & 0x7F7F7F7Fu);
    }
    if (nz1) atomicOr(&g_nzB1, 1);
    if (nz2) atomicOr(&g_nzB2, 1);
}

// B1 materialize (GENERAL PATH ONLY): fp8 residual rows of bank [n][k]
__global__ void __launch_bounds__(128) convB1_kernel(const float* __restrict__ bank) {
    if (!(g_nzB1 && g_nzB2)) return;       // consumed only by gemm1 mainloop
    const int n = blockIdx.x;              // 0..1023
    const int t = threadIdx.x;
    uint32_t* dst = reinterpret_cast<uint32_t*>(g_B1f8 + (size_t)n * KPAD);
    if (n >= C_CLS) {
        for (int u = t; u < KPAD / 4; u += 128) dst[u] = 0u;
        return;
    }
    const float m = g_m1[n];
    const float* row = bank + (size_t)n * C_CLS;
    for (int u = t; u < KPAD / 4; u += 128) {
        int k = 4 * u;
        float4 v = make_float4(0.f, 0.f, 0.f, 0.f);
        if (k + 3 < C_CLS) v = *(const float4*)(row + k);  // C_CLS % 4 == 0
        uint16_t lo = f2_fp8x2((k < C_CLS) ? (v.x - m) * SB : 0.f,
                               (k < C_CLS) ? (v.y - m) * SB : 0.f);
        uint16_t hi = f2_fp8x2((k < C_CLS) ? (v.z - m) * SB : 0.f,
                               (k < C_CLS) ? (v.w - m) * SB : 0.f);
        dst[u] = (uint32_t)lo | ((uint32_t)hi << 16);
    }
}

// T1 (GENERAL PATH ONLY): tiled transpose bank -> g_BT (fp32)
__global__ void __launch_bounds__(256) transT_kernel(const float* __restrict__ bank) {
    if (g_nzB2 == 0) return;
    __shared__ float tile[32][33];
    const int tk = blockIdx.y * 32;
    const int tj = blockIdx.x * 32;
    const int jx = threadIdx.x & 31;
    const int ky = threadIdx.x >> 5;
    #pragma unroll
    for (int s = 0; s < 4; s++) {
        int k = tk + ky + s * 8, j = tj + jx;
        tile[ky + s * 8][jx] = (k < C_CLS && j < C_CLS)
                             ? bank[(size_t)k * C_CLS + j] : 0.0f;
    }
    __syncthreads();
    #pragma unroll
    for (int s = 0; s < 4; s++) {
        int j = tj + ky + s * 8, k = tk + jx;
        g_BT[(size_t)j * KPAD + k] = tile[jx][ky + s * 8];
    }
}

// T2 materialize (GENERAL PATH ONLY): fp8 residual rows of bank^T [j][k]
__global__ void __launch_bounds__(128) convB2_kernel() {
    if (g_nzB2 == 0) return;
    const int j = blockIdx.x;
    const int t = threadIdx.x;
    uint32_t* dst = reinterpret_cast<uint32_t*>(g_B2f8 + (size_t)j * KPAD);
    if (j >= C_CLS) {
        for (int u = t; u < KPAD / 4; u += 128) dst[u] = 0u;
        return;
    }
    const float m = g_m2[j] * INV_C;
    const float* row = g_BT + (size_t)j * KPAD;
    for (int u = t; u < KPAD / 4; u += 128) {
        int k = 4 * u;
        if (k + 3 < C_CLS) {
            float4 v = *(const float4*)(row + k);
            uint16_t lo = f2_fp8x2((v.x - m) * SB, (v.y - m) * SB);
            uint16_t hi = f2_fp8x2((v.z - m) * SB, (v.w - m) * SB);
            dst[u] = (uint32_t)lo | ((uint32_t)hi << 16);
        } else {
            dst[u] = 0u;
        }
    }
}

// prep: 4 rows per 256-thread block (64 thr/row, MLP=8, streaming loads):
//   dual argmax + agreement + fused scatter-add
//   + p_tar -> fp8 A (only if gemm1's mainloop will run)
//   + FUSED uncertainty mixing -> out when nzB2 == 0 (p_vlm read exactly once)
#define RPB 4
__global__ void __launch_bounds__(256) prep_kernel(const float* __restrict__ p_tar,
                                                   const float* __restrict__ p_vlm,
                                                   float* __restrict__ out) {
    const int t    = threadIdx.x;
    const int rg   = t >> 6;             // row group 0..3
    const int g    = t & 63;             // thread within row group
    const int row  = blockIdx.x * RPB + rg;
    const int  nzB2  = g_nzB2;
    const bool needA = (g_nzB1 != 0) && (nzB2 != 0);

    const float4* pt4 = reinterpret_cast<const float4*>(p_tar + (size_t)row * C_CLS);
    const float4* pv4 = reinterpret_cast<const float4*>(p_vlm + (size_t)row * C_CLS);
    uint32_t* arow = reinterpret_cast<uint32_t*>(g_Af8 + (size_t)row * KPAD);

    // load 4 chunks per input (MLP = 8 float4 streaming loads in flight)
    float4 a[4], b[4];
    bool   val[4];
    #pragma unroll
    for (int i = 0; i < 4; i++) {
        const int kq = g + 64 * i;       // float4 index, 0..255
        val[i] = (kq < C_CLS / 4);
        if (val[i]) { a[i] = __ldcs(pt4 + kq); b[i] = __ldcs(pv4 + kq); }
        else        { a[i] = make_float4(0.f,0.f,0.f,0.f);
                      b[i] = make_float4(0.f,0.f,0.f,0.f); }
    }

    float vt = -1.0f, vv = -1.0f;
    int   it = 0,     iv = 0;
    #pragma unroll
    for (int i = 0; i < 4; i++) {
        const int k = 4 * (g + 64 * i);
        if (val[i]) {
            if (a[i].x > vt) { vt = a[i].x; it = k; }
            if (a[i].y > vt) { vt = a[i].y; it = k + 1; }
            if (a[i].z > vt) { vt = a[i].z; it = k + 2; }
            if (a[i].w > vt) { vt = a[i].w; it = k + 3; }
            if (b[i].x > vv) { vv = b[i].x; iv = k; }
            if (b[i].y > vv) { vv = b[i].y; iv = k + 1; }
            if (b[i].z > vv) { vv = b[i].z; iv = k + 2; }
            if (b[i].w > vv) { vv = b[i].w; iv = k + 3; }
        }
        if (needA) {
            const int kq = g + 64 * i;
            uint16_t lo = f2_fp8x2(a[i].x * SA, a[i].y * SA);
            uint16_t hi = f2_fp8x2(a[i].z * SA, a[i].w * SA);
            arow[kq] = (uint32_t)lo | ((uint32_t)hi << 16);
        }
        if (nzB2 == 0 && val[i]) {   // fast-path mixing, streaming store
            float4 pc = *(const float4*)(g_ptc + k);
            float4 ec = *(const float4*)(g_eutc + k);
            float4 o;
            float euv;
            euv = __expf(b[i].x * __logf(b[i].x + EPSU));
            o.x = (ec.x * pc.x + euv * b[i].x) / (ec.x + euv);
            euv = __expf(b[i].y * __logf(b[i].y + EPSU));
            o.y = (ec.y * pc.y + euv * b[i].y) / (ec.y + euv);
            euv = __expf(b[i].z * __logf(b[i].z + EPSU));
            o.z = (ec.z * pc.z + euv * b[i].z) / (ec.z + euv);
            euv = __expf(b[i].w * __logf(b[i].w + EPSU));
            o.w = (ec.w * pc.w + euv * b[i].w) / (ec.w + euv);
            __stcs(reinterpret_cast<float4*>(out + (size_t)row * C_CLS + k), o);
        }
    }

    // reduce within warp (32 lanes all in same row group)
    #pragma unroll
    for (int off = 16; off > 0; off >>= 1) {
        float ov = __shfl_down_sync(0xFFFFFFFFu, vt, off);
        int   oi = __shfl_down_sync(0xFFFFFFFFu, it, off);
        if (ov > vt || (ov == vt && oi < it)) { vt = ov; it = oi; }
        ov = __shfl_down_sync(0xFFFFFFFFu, vv, off);
        oi = __shfl_down_sync(0xFFFFFFFFu, iv, off);
        if (ov > vv || (ov == vv && oi < iv)) { vv = ov; iv = oi; }
    }
    __shared__ float swt[8], swv[8];
    __shared__ int   sit[8], siv[8];
    __shared__ int   s_lab[RPB];
    const int w = t >> 5;                 // warp id 0..7; row group rg = w>>1
    if ((t & 31) == 0) { swt[w] = vt; sit[w] = it; swv[w] = vv; siv[w] = iv; }
    __syncthreads();
    if (g == 0) {                         // one finalizer per row group
        const int w0 = 2 * rg;
        float bt = swt[w0], bv = swv[w0];
        int   bi = sit[w0], bj = siv[w0];
        if (swt[w0 + 1] > bt || (swt[w0 + 1] == bt && sit[w0 + 1] < bi))
            { bt = swt[w0 + 1]; bi = sit[w0 + 1]; }
        if (swv[w0 + 1] > bv || (swv[w0 + 1] == bv && siv[w0 + 1] < bj))
            { bv = swv[w0 + 1]; bj = siv[w0 + 1]; }
        if (bi == bj) { s_lab[rg] = bi; atomicAdd(&g_count[bi], 1.0f); }
        else          { s_lab[rg] = -1; }
    }
    __syncthreads();
    const int c = s_lab[rg];
    if (c >= 0) {   // fused scatter (rare: ~B/C rows agree)
        float* dst = g_sums + (size_t)c * C_CLS;
        #pragma unroll
        for (int i = 0; i < 4; i++) {
            if (val[i]) {
                const int k = 4 * (g + 64 * i);
                atomicAdd(dst + k + 0, a[i].x);
                atomicAdd(dst + k + 1, a[i].y);
                atomicAdd(dst + k + 2, a[i].z);
                atomicAdd(dst + k + 3, a[i].w);
            }
        }
    }
}

__global__ void bank_kernel(const float* __restrict__ bank,
                            const float* __restrict__ alpha,
                            float* __restrict__ out_bank) {
    int i = blockIdx.x * blockDim.x + threadIdx.x;
    if (i >= C_CLS * C_CLS) return;
    int   c   = i / C_CLS;
    float a   = alpha[0];
    float cnt = g_count[c];
    float b   = bank[i];
    out_bank[i] = (cnt > 0.0f) ? (a * b + (1.0f - a) * (g_sums[i] / cnt)) : b;
}

// ---------------------------------------------------------------------------
// fp8 HMMA GEMM (NT): D[bm:+128, bn:+64] = A * B^T (residual part)
// 128 thr, 4 warps, warp tile 32x64, cp.async 3-stage, 4 CTAs/SM.
// FAST PATHS (exact):
//  - nzB2==0            -> both modes exit (E/rowsum dead; out written by prep)
//  - nzB==0 (general)   -> mainloop skipped, acc stays +0 (bit-identical)
#define BM     128
#define BN     64
#define BKB    64                    // k bytes per chunk
#define STAGES 3
#define LDSPB  80                    // padded smem row stride (bytes)
#define NCH    (KPAD / BKB)          // 16
#define STA    (BM * LDSPB)          // 10240
#define STB    (BN * LDSPB)          // 5120
#define STT    (STA + STB)           // 15360
#define SMEMT  (STAGES * STT)        // 46080

__global__ void __launch_bounds__(128, 4)
gemm_fp8(const float* __restrict__ p_vlm,
         float* __restrict__ out,
         int mode) {
    extern __shared__ char smem[];
    const uint32_t sb = smem_u32(smem);

    const int nzB2 = g_nzB2;
    if (nzB2 == 0) return;   // fast path handled entirely by prep_kernel

    const uint8_t* __restrict__ A  = (mode == 1) ? g_Af8  : g_Ef8;
    const uint8_t* __restrict__ Bm = (mode == 1) ? g_B1f8 : g_B2f8;
    const int nzB = (mode == 1) ? g_nzB1 : nzB2;

    const int t   = threadIdx.x;
    const int wid = t >> 5;              // 0..3 -> m offset wid*32
    const int l   = t & 31;
    const int bm  = blockIdx.y * BM;
    const int bn  = blockIdx.x * BN;

    const int r = t >> 2, u = t & 3;     // loader: 32 rows x 4x16B per pass

    float acc[2][8][4];
    #pragma unroll
    for (int mi = 0; mi < 2; mi++)
        #pragma unroll
        for (int ni = 0; ni < 8; ni++)
            #pragma unroll
            for (int kk = 0; kk < 4; kk++) acc[mi][ni][kk] = 0.0f;

    if (nzB) {   // residual GEMM only when B residual is not value-zero
        const int aRow = wid * 32 + (l & 15);
        const int aOff = (l & 16) ? 16 : 0;   // bytes
        const int bRow = (l & 7) + ((l & 16) ? 8 : 0);
        const int bOff = (l & 8) ? 16 : 0;    // bytes

        auto load_stage = [&](int chunk, int buf) {
            const int kc = chunk * BKB;
            const uint32_t dA = sb + buf * STT;
            const uint32_t dB = dA + STA;
            #pragma unroll
            for (int i = 0; i < 4; i++) {     // A: 128 rows
                int rr = r + 32 * i;
                CP16(dA + rr * LDSPB + u * 16,
                     (const void*)(A + (size_t)(bm + rr) * KPAD + kc + u * 16));
            }
            #pragma unroll
            for (int i = 0; i < 2; i++) {     // B: 64 rows
                int rr = r + 32 * i;
                CP16(dB + rr * LDSPB + u * 16,
                     (const void*)(Bm + (size_t)(bn + rr) * KPAD + kc + u * 16));
            }
        };

        #pragma unroll
        for (int s = 0; s < STAGES - 1; ++s) { load_stage(s, s); CP_COMMIT(); }

        for (int c = 0; c < NCH; ++c) {
            CP_WAIT1();
            __syncthreads();

            const int nc_ = c + STAGES - 1;
            if (nc_ < NCH) load_stage(nc_, nc_ % STAGES);
            CP_COMMIT();

            const int buf = c % STAGES;
            const uint32_t baseA = sb + buf * STT;
            const uint32_t baseB = baseA + STA;

            #pragma unroll
            for (int s = 0; s < 2; ++s) {
                uint32_t af[2][4];
                #pragma unroll
                for (int mi = 0; mi < 2; mi++)
                    ldmx4(af[mi], baseA + (aRow + mi * 16) * LDSPB + s * 32 + aOff);
                uint32_t bf[4][4];
                #pragma unroll
                for (int g2 = 0; g2 < 4; g2++)
                    ldmx4(bf[g2], baseB + (bRow + g2 * 16) * LDSPB + s * 32 + bOff);
                #pragma unroll
                for (int mi = 0; mi < 2; mi++)
                    #pragma unroll
                    for (int g2 = 0; g2 < 4; g2++) {
                        mma_fp8(acc[mi][2 * g2],     af[mi], bf[g2][0], bf[g2][1]);
                        mma_fp8(acc[mi][2 * g2 + 1], af[mi], bf[g2][2], bf[g2][3]);
                    }
            }
        }
    }

    // ---- epilogue (general path) ----
    // rows: bm + wid*32 + mi*16 + (l>>2) + h*8 ; cols: bn + ni*8 + (l&3)*2
    if (mode == 1) {
        #pragma unroll
        for (int mi = 0; mi < 2; mi++) {
            #pragma unroll
            for (int h = 0; h < 2; h++) {
                const int row = bm + wid * 32 + mi * 16 + (l >> 2) + h * 8;
                float rs = 0.0f;
                #pragma unroll
                for (int ni = 0; ni < 8; ni++) {
                    const int col = bn + ni * 8 + (l & 3) * 2;
                    float e0 = 0.0f, e1 = 0.0f;
                    if (col < C_CLS)
                        e0 = __expf((g_m1[col] + acc[mi][ni][h * 2 + 0] * DEQ) * NORMF);
                    if (col + 1 < C_CLS)
                        e1 = __expf((g_m1[col + 1] + acc[mi][ni][h * 2 + 1] * DEQ) * NORMF);
                    *(uint16_t*)&g_Ef8[(size_t)row * KPAD + col] =
                        f2_fp8x2(e0 * SA, e1 * SA);
                    rs += e0 + e1;
                }
                rs += __shfl_xor_sync(0xFFFFFFFFu, rs, 1);
                rs += __shfl_xor_sync(0xFFFFFFFFu, rs, 2);
                if ((l & 3) == 0) atomicAdd(&g_rowsum[row], rs);
            }
        }
    } else {
        #pragma unroll
        for (int mi = 0; mi < 2; mi++) {
            #pragma unroll
            for (int h = 0; h < 2; h++) {
                const int row = bm + wid * 32 + mi * 16 + (l >> 2) + h * 8;
                const float inv = 1.0f / g_rowsum[row];
                const float* pvrow = p_vlm + (size_t)row * C_CLS;
                float*       orow  = out   + (size_t)row * C_CLS;
                #pragma unroll
                for (int ni = 0; ni < 8; ni++) {
                    const int col = bn + ni * 8 + (l & 3) * 2;
                    #pragma unroll
                    for (int e = 0; e < 2; e++) {
                        int n = col + e;
                        if (n < C_CLS) {
                            float pt  = g_m2[n] * INV_C
                                      + acc[mi][ni][h * 2 + e] * DEQ * inv;
                            float pv  = __ldg(pvrow + n);
                            float eut = __expf(pt * __logf(pt + EPSU));
                            float euv = __expf(pv * __logf(pv + EPSU));
                            orow[n] = (eut * pt + euv * pv) / (eut + euv);
                        }
                    }
                }
            }
        }
    }
}

// ---------------------------------------------------------------------------
extern "C" void kernel_launch(void* const* d_in, const int* in_sizes, int n_in,
                              void* d_out, int out_size) {
    const float* p_tar = (const float*)d_in[0];
    const float* p_vlm = (const float*)d_in[1];
    const float* alpha = (const float*)d_in[2];
    const float* bank  = (const float*)d_in[3];
    float* out      = (float*)d_out;                       // p_mix [B,C]
    float* out_bank = out + (size_t)B_ROWS * C_CLS;        // bank_new [C,C]

    static int attr_set = 0;
    if (!attr_set) {
        cudaFuncSetAttribute(gemm_fp8, cudaFuncAttributeMaxDynamicSharedMemorySize,
                             SMEMT);
        attr_set = 1;
    }

    dim3 gg(KPAD / BN, B_ROWS / BM);  // (16, 256)

    pre_kernel<<<PRE_BLOCKS, 128>>>(bank);                        // 1
    flags_kernel<<<C_CLS, 128>>>(bank);                           // 2
    prep_kernel<<<B_ROWS / RPB, 256>>>(p_tar, p_vlm, out);        // 3
    convB1_kernel<<<KPAD, 128>>>(bank);                           // 4 (general only)
    transT_kernel<<<dim3(32, 32), 256>>>(bank);                   // 5 (general only)
    convB2_kernel<<<KPAD, 128>>>();                               // 6 (general only)
    gemm_fp8<<<gg, 128, SMEMT>>>(nullptr, nullptr, 1);            // 7 (general only)
    gemm_fp8<<<gg, 128, SMEMT>>>(p_vlm, out, 2);                  // 8 (general only)
    bank_kernel<<<(C_CLS * C_CLS + 255) / 256, 256>>>(bank, alpha, out_bank); // 9
}

// round 16
// speedup vs baseline: 1.0306x; 1.0306x over previous
#include <cuda_runtime.h>
#include <cuda_bf16.h>
#include <cuda_fp8.h>
#include <cstdint>
#include <math.h>

#define B_ROWS 32768
#define C_CLS  1000
#define KPAD   1024
#define EPSU   1e-6f
#define NORMF  0.031622776601683794f   // 1/sqrt(1000)
#define INV_C  0.001f
#define SA     128.0f                  // fp8 scale for A / E
#define SB     256.0f                  // fp8 scale for centered B residuals
#define DEQ    (1.0f / (128.0f * 256.0f))

// ---------------- scratch (__device__ globals; no allocations) --------------
__device__ uint8_t g_Af8[(size_t)B_ROWS * KPAD];   // p_tar  fp8 x128, padded
__device__ uint8_t g_Ef8[(size_t)B_ROWS * KPAD];   // E      fp8 x128, padded
__device__ uint8_t g_B1f8[(size_t)KPAD * KPAD];    // (bank - m1) x256  [n][k]
__device__ uint8_t g_B2f8[(size_t)KPAD * KPAD];    // (bank^T - m2) x256 [j][k]
__device__ float   g_m1[KPAD];                     // row MEANS of bank
__device__ float   g_m2[KPAD];                     // raw col SUMS of bank
__device__ float   g_ptc[KPAD];                    // fast-path pt per column
__device__ float   g_eutc[KPAD];                   // fast-path eut per column
__device__ float   g_rowsum[B_ROWS];
__device__ float   g_sums[(size_t)C_CLS * C_CLS];
__device__ float   g_count[C_CLS];
__device__ int     g_nzB1;                         // residual B1 has nonzero?
__device__ int     g_nzB2;                         // residual B2 has nonzero?

// ---------------- helpers ----------------------------------------------------
__device__ __forceinline__ uint16_t f2_fp8x2(float lo, float hi) {
    __nv_fp8x2_storage_t r =
        __nv_cvt_float2_to_fp8x2(make_float2(lo, hi), __NV_SATFINITE, __NV_E4M3);
    return (uint16_t)r;
}
__device__ __forceinline__ uint32_t smem_u32(const void* p) {
    uint32_t a;
    asm("{ .reg .u64 t; cvta.to.shared.u64 t, %1; cvt.u32.u64 %0, t; }"
        : "=r"(a) : "l"(p));
    return a;
}
__device__ __forceinline__ void ldmx4(uint32_t* r, uint32_t addr) {
    asm volatile("ldmatrix.sync.aligned.m8n8.x4.shared.b16 {%0,%1,%2,%3}, [%4];"
                 : "=r"(r[0]), "=r"(r[1]), "=r"(r[2]), "=r"(r[3]) : "r"(addr));
}
__device__ __forceinline__ void mma_fp8(float* c, const uint32_t* a,
                                        uint32_t b0, uint32_t b1) {
    asm volatile("mma.sync.aligned.m16n8k32.row.col.f32.e4m3.e4m3.f32 "
                 "{%0,%1,%2,%3}, {%4,%5,%6,%7}, {%8,%9}, {%0,%1,%2,%3};"
                 : "+f"(c[0]), "+f"(c[1]), "+f"(c[2]), "+f"(c[3])
                 : "r"(a[0]), "r"(a[1]), "r"(a[2]), "r"(a[3]), "r"(b0), "r"(b1));
}
#define CP16(dst, src) \
    asm volatile("cp.async.cg.shared.global [%0], [%1], 16;" :: "r"(dst), "l"(src))
#define CP_COMMIT() asm volatile("cp.async.commit_group;")
#define CP_WAIT1()  asm volatile("cp.async.wait_group 1;")

// ---------------------------------------------------------------------------
// pre: m1 row means (blocks 0..999) + m2 col sums, deterministic (1000..1031)
//      + zero g_sums/g_count/g_rowsum/flags (1032..1287)
#define PRE_BLOCKS (1000 + 32 + 256)
__global__ void __launch_bounds__(128) pre_kernel(const float* __restrict__ bank) {
    const int b = blockIdx.x;
    const int t = threadIdx.x;
    if (b < C_CLS) {                       // ---- m1[b] = mean of row b ----
        const float* row = bank + (size_t)b * C_CLS;
        float s = 0.0f;
        for (int k = t; k < C_CLS; k += 128) s += row[k];
        #pragma unroll
        for (int o = 16; o > 0; o >>= 1) s += __shfl_xor_sync(0xFFFFFFFFu, s, o);
        __shared__ float sw[4];
        if ((t & 31) == 0) sw[t >> 5] = s;
        __syncthreads();
        if (t == 0) g_m1[b] = (sw[0] + sw[1] + sw[2] + sw[3]) * INV_C;
    } else if (b < C_CLS + 32) {           // ---- m2: 32 cols per block ----
        const int j  = (b - C_CLS) * 32 + (t & 31);
        const int rs = t >> 5;             // 0..3
        float s = 0.0f;
        if (j < C_CLS)
            for (int k = rs; k < C_CLS; k += 4)
                s += bank[(size_t)k * C_CLS + j];
        __shared__ float sm[4][32];
        sm[rs][t & 31] = s;
        __syncthreads();
        if (rs == 0 && j < C_CLS)
            g_m2[j] = sm[0][t & 31] + sm[1][t & 31] + sm[2][t & 31] + sm[3][t & 31];
    } else {                               // ---- zero scratch ----
        const int zi = (b - C_CLS - 32) * 128 + t;    // 0..32767
        float4 z4 = make_float4(0.f, 0.f, 0.f, 0.f);
        for (int i = zi; i < (C_CLS * C_CLS) / 4; i += 256 * 128)
            reinterpret_cast<float4*>(g_sums)[i] = z4;
        if (zi < C_CLS) g_count[zi] = 0.0f;
        g_rowsum[zi] = 0.0f;
        if (zi == 0) { g_nzB1 = 0; g_nzB2 = 0; }
    }
}

// flags: one 4MB pass over bank -> nzB1/nzB2 (bit-exact same fp8 rounding as
// the materializer, same g_m1/g_m2 inputs) + ptc/eutc (block 0)
__global__ void __launch_bounds__(128) flags_kernel(const float* __restrict__ bank) {
    const int k = blockIdx.x;              // bank row 0..999
    const int t = threadIdx.x;
    if (k == 0) {
        for (int j = t; j < C_CLS; j += 128) {
            float m = g_m2[j] * INV_C;
            g_ptc[j]  = m;
            g_eutc[j] = __expf(m * __logf(m + EPSU));
        }
    }
    const float m1k = g_m1[k];
    const float4* row = reinterpret_cast<const float4*>(bank + (size_t)k * C_CLS);
    uint32_t nz1 = 0u, nz2 = 0u;
    for (int u = t; u < C_CLS / 4; u += 128) {
        float4 v = row[u];
        const int j = 4 * u;
        uint32_t p1 = (uint32_t)f2_fp8x2((v.x - m1k) * SB, (v.y - m1k) * SB)
                    | ((uint32_t)f2_fp8x2((v.z - m1k) * SB, (v.w - m1k) * SB) << 16);
        nz1 |= (p1 & 0x7F7F7F7Fu);
        float ma = g_m2[j + 0] * INV_C;
        float mb = g_m2[j + 1] * INV_C;
        float mc = g_m2[j + 2] * INV_C;
        float md = g_m2[j + 3] * INV_C;
        uint32_t p2 = (uint32_t)f2_fp8x2((v.x - ma) * SB, (v.y - mb) * SB)
                    | ((uint32_t)f2_fp8x2((v.z - mc) * SB, (v.w - md) * SB) << 16);
        nz2 |= (p2 & 0x7F7F7F7Fu);
    }
    if (nz1) atomicOr(&g_nzB1, 1);
    if (nz2) atomicOr(&g_nzB2, 1);
}

// materialize (GENERAL PATH ONLY): block n writes fp8 residual row n of BOTH
//   B1[n][k] = fp8((bank[n][k] - m1[n]) * SB)        (only if nzB1 != 0)
//   B2[n][k] = fp8((bank[k][n] - m2[n]/C) * SB)      (column gather; L2-resident)
__global__ void __launch_bounds__(128) materialize_kernel(const float* __restrict__ bank) {
    if (g_nzB2 == 0) return;               // fast path: nothing consumed
    const int n = blockIdx.x;               // 0..1023
    const int t = threadIdx.x;
    const bool doB1 = (g_nzB1 != 0);
    uint32_t* d1 = reinterpret_cast<uint32_t*>(g_B1f8 + (size_t)n * KPAD);
    uint32_t* d2 = reinterpret_cast<uint32_t*>(g_B2f8 + (size_t)n * KPAD);
    if (n >= C_CLS) {
        for (int u = t; u < KPAD / 4; u += 128) { if (doB1) d1[u] = 0u; d2[u] = 0u; }
        return;
    }
    const float m1n = g_m1[n];
    const float m2n = g_m2[n] * INV_C;
    const float* row = bank + (size_t)n * C_CLS;
    for (int u = t; u < KPAD / 4; u += 128) {
        int k = 4 * u;
        if (k + 3 < C_CLS) {               // C_CLS % 4 == 0
            if (doB1) {
                float4 v = *(const float4*)(row + k);
                d1[u] = (uint32_t)f2_fp8x2((v.x - m1n) * SB, (v.y - m1n) * SB)
                      | ((uint32_t)f2_fp8x2((v.z - m1n) * SB, (v.w - m1n) * SB) << 16);
            }
            float c0 = bank[(size_t)(k + 0) * C_CLS + n];
            float c1 = bank[(size_t)(k + 1) * C_CLS + n];
            float c2 = bank[(size_t)(k + 2) * C_CLS + n];
            float c3 = bank[(size_t)(k + 3) * C_CLS + n];
            d2[u] = (uint32_t)f2_fp8x2((c0 - m2n) * SB, (c1 - m2n) * SB)
                  | ((uint32_t)f2_fp8x2((c2 - m2n) * SB, (c3 - m2n) * SB) << 16);
        } else {
            if (doB1) d1[u] = 0u;
            d2[u] = 0u;
        }
    }
}

// prep: 4 rows per 256-thread block (64 thr/row, MLP=8, streaming loads):
//   dual argmax + agreement + fused scatter-add
//   + p_tar -> fp8 A (only if gemm1's mainloop will run)
//   + FUSED uncertainty mixing -> out when nzB2 == 0 (p_vlm read exactly once)
#define RPB 4
__global__ void __launch_bounds__(256) prep_kernel(const float* __restrict__ p_tar,
                                                   const float* __restrict__ p_vlm,
                                                   float* __restrict__ out) {
    const int t    = threadIdx.x;
    const int rg   = t >> 6;             // row group 0..3
    const int g    = t & 63;             // thread within row group
    const int row  = blockIdx.x * RPB + rg;
    const int  nzB2  = g_nzB2;
    const bool needA = (g_nzB1 != 0) && (nzB2 != 0);

    const float4* pt4 = reinterpret_cast<const float4*>(p_tar + (size_t)row * C_CLS);
    const float4* pv4 = reinterpret_cast<const float4*>(p_vlm + (size_t)row * C_CLS);
    uint32_t* arow = reinterpret_cast<uint32_t*>(g_Af8 + (size_t)row * KPAD);

    float4 a[4], b[4];
    bool   val[4];
    #pragma unroll
    for (int i = 0; i < 4; i++) {
        const int kq = g + 64 * i;       // float4 index, 0..255
        val[i] = (kq < C_CLS / 4);
        if (val[i]) { a[i] = __ldcs(pt4 + kq); b[i] = __ldcs(pv4 + kq); }
        else        { a[i] = make_float4(0.f,0.f,0.f,0.f);
                      b[i] = make_float4(0.f,0.f,0.f,0.f); }
    }

    float vt = -1.0f, vv = -1.0f;
    int   it = 0,     iv = 0;
    #pragma unroll
    for (int i = 0; i < 4; i++) {
        const int k = 4 * (g + 64 * i);
        if (val[i]) {
            if (a[i].x > vt) { vt = a[i].x; it = k; }
            if (a[i].y > vt) { vt = a[i].y; it = k + 1; }
            if (a[i].z > vt) { vt = a[i].z; it = k + 2; }
            if (a[i].w > vt) { vt = a[i].w; it = k + 3; }
            if (b[i].x > vv) { vv = b[i].x; iv = k; }
            if (b[i].y > vv) { vv = b[i].y; iv = k + 1; }
            if (b[i].z > vv) { vv = b[i].z; iv = k + 2; }
            if (b[i].w > vv) { vv = b[i].w; iv = k + 3; }
        }
        if (needA) {
            const int kq = g + 64 * i;
            uint16_t lo = f2_fp8x2(a[i].x * SA, a[i].y * SA);
            uint16_t hi = f2_fp8x2(a[i].z * SA, a[i].w * SA);
            arow[kq] = (uint32_t)lo | ((uint32_t)hi << 16);
        }
        if (nzB2 == 0 && val[i]) {   // fast-path mixing, streaming store
            float4 pc = *(const float4*)(g_ptc + k);
            float4 ec = *(const float4*)(g_eutc + k);
            float4 o;
            float euv;
            euv = __expf(b[i].x * __logf(b[i].x + EPSU));
            o.x = (ec.x * pc.x + euv * b[i].x) / (ec.x + euv);
            euv = __expf(b[i].y * __logf(b[i].y + EPSU));
            o.y = (ec.y * pc.y + euv * b[i].y) / (ec.y + euv);
            euv = __expf(b[i].z * __logf(b[i].z + EPSU));
            o.z = (ec.z * pc.z + euv * b[i].z) / (ec.z + euv);
            euv = __expf(b[i].w * __logf(b[i].w + EPSU));
            o.w = (ec.w * pc.w + euv * b[i].w) / (ec.w + euv);
            __stcs(reinterpret_cast<float4*>(out + (size_t)row * C_CLS + k), o);
        }
    }

    #pragma unroll
    for (int off = 16; off > 0; off >>= 1) {
        float ov = __shfl_down_sync(0xFFFFFFFFu, vt, off);
        int   oi = __shfl_down_sync(0xFFFFFFFFu, it, off);
        if (ov > vt || (ov == vt && oi < it)) { vt = ov; it = oi; }
        ov = __shfl_down_sync(0xFFFFFFFFu, vv, off);
        oi = __shfl_down_sync(0xFFFFFFFFu, iv, off);
        if (ov > vv || (ov == vv && oi < iv)) { vv = ov; iv = oi; }
    }
    __shared__ float swt[8], swv[8];
    __shared__ int   sit[8], siv[8];
    __shared__ int   s_lab[RPB];
    const int w = t >> 5;                 // warp id 0..7; row group rg = w>>1
    if ((t & 31) == 0) { swt[w] = vt; sit[w] = it; swv[w] = vv; siv[w] = iv; }
    __syncthreads();
    if (g == 0) {                         // one finalizer per row group
        const int w0 = 2 * rg;
        float bt = swt[w0], bv = swv[w0];
        int   bi = sit[w0], bj = siv[w0];
        if (swt[w0 + 1] > bt || (swt[w0 + 1] == bt && sit[w0 + 1] < bi))
            { bt = swt[w0 + 1]; bi = sit[w0 + 1]; }
        if (swv[w0 + 1] > bv || (swv[w0 + 1] == bv && siv[w0 + 1] < bj))
            { bv = swv[w0 + 1]; bj = siv[w0 + 1]; }
        if (bi == bj) { s_lab[rg] = bi; atomicAdd(&g_count[bi], 1.0f); }
        else          { s_lab[rg] = -1; }
    }
    __syncthreads();
    const int c = s_lab[rg];
    if (c >= 0) {   // fused scatter (rare: ~B/C rows agree)
        float* dst = g_sums + (size_t)c * C_CLS;
        #pragma unroll
        for (int i = 0; i < 4; i++) {
            if (val[i]) {
                const int k = 4 * (g + 64 * i);
                atomicAdd(dst + k + 0, a[i].x);
                atomicAdd(dst + k + 1, a[i].y);
                atomicAdd(dst + k + 2, a[i].z);
                atomicAdd(dst + k + 3, a[i].w);
            }
        }
    }
}

__global__ void bank_kernel(const float* __restrict__ bank,
                            const float* __restrict__ alpha,
                            float* __restrict__ out_bank) {
    int i = blockIdx.x * blockDim.x + threadIdx.x;
    if (i >= C_CLS * C_CLS) return;
    int   c   = i / C_CLS;
    float a   = alpha[0];
    float cnt = g_count[c];
    float b   = bank[i];
    out_bank[i] = (cnt > 0.0f) ? (a * b + (1.0f - a) * (g_sums[i] / cnt)) : b;
}

// ---------------------------------------------------------------------------
// fp8 HMMA GEMM (NT): D[bm:+128, bn:+64] = A * B^T (residual part)
// 128 thr, 4 warps, warp tile 32x64, cp.async 3-stage, 4 CTAs/SM.
// FAST PATHS (exact):
//  - nzB2==0            -> both modes exit (E/rowsum dead; out written by prep)
//  - nzB==0 (general)   -> mainloop skipped, acc stays +0 (bit-identical)
#define BM     128
#define BN     64
#define BKB    64                    // k bytes per chunk
#define STAGES 3
#define LDSPB  80                    // padded smem row stride (bytes)
#define NCH    (KPAD / BKB)          // 16
#define STA    (BM * LDSPB)          // 10240
#define STB    (BN * LDSPB)          // 5120
#define STT    (STA + STB)           // 15360
#define SMEMT  (STAGES * STT)        // 46080

__global__ void __launch_bounds__(128, 4)
gemm_fp8(const float* __restrict__ p_vlm,
         float* __restrict__ out,
         int mode) {
    extern __shared__ char smem[];
    const uint32_t sb = smem_u32(smem);

    const int nzB2 = g_nzB2;
    if (nzB2 == 0) return;   // fast path handled entirely by prep_kernel

    const uint8_t* __restrict__ A  = (mode == 1) ? g_Af8  : g_Ef8;
    const uint8_t* __restrict__ Bm = (mode == 1) ? g_B1f8 : g_B2f8;
    const int nzB = (mode == 1) ? g_nzB1 : nzB2;

    const int t   = threadIdx.x;
    const int wid = t >> 5;              // 0..3 -> m offset wid*32
    const int l   = t & 31;
    const int bm  = blockIdx.y * BM;
    const int bn  = blockIdx.x * BN;

    const int r = t >> 2, u = t & 3;     // loader: 32 rows x 4x16B per pass

    float acc[2][8][4];
    #pragma unroll
    for (int mi = 0; mi < 2; mi++)
        #pragma unroll
        for (int ni = 0; ni < 8; ni++)
            #pragma unroll
            for (int kk = 0; kk < 4; kk++) acc[mi][ni][kk] = 0.0f;

    if (nzB) {   // residual GEMM only when B residual is not value-zero
        const int aRow = wid * 32 + (l & 15);
        const int aOff = (l & 16) ? 16 : 0;   // bytes
        const int bRow = (l & 7) + ((l & 16) ? 8 : 0);
        const int bOff = (l & 8) ? 16 : 0;    // bytes

        auto load_stage = [&](int chunk, int buf) {
            const int kc = chunk * BKB;
            const uint32_t dA = sb + buf * STT;
            const uint32_t dB = dA + STA;
            #pragma unroll
            for (int i = 0; i < 4; i++) {     // A: 128 rows
                int rr = r + 32 * i;
                CP16(dA + rr * LDSPB + u * 16,
                     (const void*)(A + (size_t)(bm + rr) * KPAD + kc + u * 16));
            }
            #pragma unroll
            for (int i = 0; i < 2; i++) {     // B: 64 rows
                int rr = r + 32 * i;
                CP16(dB + rr * LDSPB + u * 16,
                     (const void*)(Bm + (size_t)(bn + rr) * KPAD + kc + u * 16));
            }
        };

        #pragma unroll
        for (int s = 0; s < STAGES - 1; ++s) { load_stage(s, s); CP_COMMIT(); }

        for (int c = 0; c < NCH; ++c) {
            CP_WAIT1();
            __syncthreads();

            const int nc_ = c + STAGES - 1;
            if (nc_ < NCH) load_stage(nc_, nc_ % STAGES);
            CP_COMMIT();

            const int buf = c % STAGES;
            const uint32_t baseA = sb + buf * STT;
            const uint32_t baseB = baseA + STA;

            #pragma unroll
            for (int s = 0; s < 2; ++s) {
                uint32_t af[2][4];
                #pragma unroll
                for (int mi = 0; mi < 2; mi++)
                    ldmx4(af[mi], baseA + (aRow + mi * 16) * LDSPB + s * 32 + aOff);
                uint32_t bf[4][4];
                #pragma unroll
                for (int g2 = 0; g2 < 4; g2++)
                    ldmx4(bf[g2], baseB + (bRow + g2 * 16) * LDSPB + s * 32 + bOff);
                #pragma unroll
                for (int mi = 0; mi < 2; mi++)
                    #pragma unroll
                    for (int g2 = 0; g2 < 4; g2++) {
                        mma_fp8(acc[mi][2 * g2],     af[mi], bf[g2][0], bf[g2][1]);
                        mma_fp8(acc[mi][2 * g2 + 1], af[mi], bf[g2][2], bf[g2][3]);
                    }
            }
        }
    }

    // ---- epilogue (general path) ----
    // rows: bm + wid*32 + mi*16 + (l>>2) + h*8 ; cols: bn + ni*8 + (l&3)*2
    if (mode == 1) {
        #pragma unroll
        for (int mi = 0; mi < 2; mi++) {
            #pragma unroll
            for (int h = 0; h < 2; h++) {
                const int row = bm + wid * 32 + mi * 16 + (l >> 2) + h * 8;
                float rs = 0.0f;
                #pragma unroll
                for (int ni = 0; ni < 8; ni++) {
                    const int col = bn + ni * 8 + (l & 3) * 2;
                    float e0 = 0.0f, e1 = 0.0f;
                    if (col < C_CLS)
                        e0 = __expf((g_m1[col] + acc[mi][ni][h * 2 + 0] * DEQ) * NORMF);
                    if (col + 1 < C_CLS)
                        e1 = __expf((g_m1[col + 1] + acc[mi][ni][h * 2 + 1] * DEQ) * NORMF);
                    *(uint16_t*)&g_Ef8[(size_t)row * KPAD + col] =
                        f2_fp8x2(e0 * SA, e1 * SA);
                    rs += e0 + e1;
                }
                rs += __shfl_xor_sync(0xFFFFFFFFu, rs, 1);
                rs += __shfl_xor_sync(0xFFFFFFFFu, rs, 2);
                if ((l & 3) == 0) atomicAdd(&g_rowsum[row], rs);
            }
        }
    } else {
        #pragma unroll
        for (int mi = 0; mi < 2; mi++) {
            #pragma unroll
            for (int h = 0; h < 2; h++) {
                const int row = bm + wid * 32 + mi * 16 + (l >> 2) + h * 8;
                const float inv = 1.0f / g_rowsum[row];
                const float* pvrow = p_vlm + (size_t)row * C_CLS;
                float*       orow  = out   + (size_t)row * C_CLS;
                #pragma unroll
                for (int ni = 0; ni < 8; ni++) {
                    const int col = bn + ni * 8 + (l & 3) * 2;
                    #pragma unroll
                    for (int e = 0; e < 2; e++) {
                        int n = col + e;
                        if (n < C_CLS) {
                            float pt  = g_m2[n] * INV_C
                                      + acc[mi][ni][h * 2 + e] * DEQ * inv;
                            float pv  = __ldg(pvrow + n);
                            float eut = __expf(pt * __logf(pt + EPSU));
                            float euv = __expf(pv * __logf(pv + EPSU));
                            orow[n] = (eut * pt + euv * pv) / (eut + euv);
                        }
                    }
                }
            }
        }
    }
}

// ---------------------------------------------------------------------------
extern "C" void kernel_launch(void* const* d_in, const int* in_sizes, int n_in,
                              void* d_out, int out_size) {
    const float* p_tar = (const float*)d_in[0];
    const float* p_vlm = (const float*)d_in[1];
    const float* alpha = (const float*)d_in[2];
    const float* bank  = (const float*)d_in[3];
    float* out      = (float*)d_out;                       // p_mix [B,C]
    float* out_bank = out + (size_t)B_ROWS * C_CLS;        // bank_new [C,C]

    static int attr_set = 0;
    if (!attr_set) {
        cudaFuncSetAttribute(gemm_fp8, cudaFuncAttributeMaxDynamicSharedMemorySize,
                             SMEMT);
        attr_set = 1;
    }

    dim3 gg(KPAD / BN, B_ROWS / BM);  // (16, 256)

    pre_kernel<<<PRE_BLOCKS, 128>>>(bank);                        // 1
    flags_kernel<<<C_CLS, 128>>>(bank);                           // 2
    prep_kernel<<<B_ROWS / RPB, 256>>>(p_tar, p_vlm, out);        // 3
    materialize_kernel<<<KPAD, 128>>>(bank);                      // 4 (general only)
    gemm_fp8<<<gg, 128, SMEMT>>>(nullptr, nullptr, 1);            // 5 (general only)
    gemm_fp8<<<gg, 128, SMEMT>>>(p_vlm, out, 2);                  // 6 (general only)
    bank_kernel<<<(C_CLS * C_CLS + 255) / 256, 256>>>(bank, alpha, out_bank); // 7
}